// round 12
// baseline (speedup 1.0000x reference)
#include <cuda_runtime.h>
#include <cstddef>

#define N_TOKENS 131072
#define TM 128
#define NTILES (N_TOKENS / TM)     // 1024
#define THREADS 256
#define GRID 148

// ---- shared memory layout (floats) ----
// Wall 64x640 | sA 128 tok x 68 (token-major) | D1 64x64 | D2 64x32 | D3 32x64
#define WALL_SZ   (64 * 640)
#define SA_STRIDE 68
#define SA_SZ     (TM * SA_STRIDE)
#define SMEM_FLOATS (WALL_SZ + SA_SZ + 64*64 + 64*32 + 32*64)
#define SMEM_BYTES (SMEM_FLOATS * 4)   // 231424 B < 232448 limit

typedef unsigned long long u64;

__device__ __forceinline__ u64 pack2(float lo, float hi) {
    u64 r; asm("mov.b64 %0, {%1, %2};" : "=l"(r) : "f"(lo), "f"(hi)); return r;
}
__device__ __forceinline__ void unpack2(u64 v, float& lo, float& hi) {
    asm("mov.b64 {%0, %1}, %2;" : "=f"(lo), "=f"(hi) : "l"(v));
}
__device__ __forceinline__ u64 ffma2(u64 a, u64 b, u64 c) {
    u64 d; asm("fma.rn.f32x2 %0, %1, %2, %3;" : "=l"(d) : "l"(a), "l"(b), "l"(c)); return d;
}

// Packed weight matrix Wall[64 j][640 c], built per-launch by prep kernel.
// c in [0,64): key_W ; [64,128): value_W ; [128,576): T_W (p-major, i minor) ; [576,640): T_b
__device__ float g_Wall[64 * 640];

__global__ void prep_kernel(const float* __restrict__ keyW, const float* __restrict__ valW,
                            const float* __restrict__ TW,   const float* __restrict__ Tb) {
    int idx = blockIdx.x * blockDim.x + threadIdx.x;
    if (idx >= 64 * 640) return;
    int j = idx / 640;
    int c = idx % 640;
    float w;
    if (c < 64)       w = keyW[j * 64 + c];
    else if (c < 128) w = valW[j * 64 + (c - 64)];
    else if (c < 576) { int p = (c - 128) >> 6; int i = c & 63; w = TW[p * 4096 + i * 64 + j]; }
    else              { int i = c - 576;                        w = Tb[i * 64 + j]; }
    g_Wall[idx] = w;
}

__global__ void __launch_bounds__(THREADS, 1)
fused_kernel(const float* __restrict__ kv_in, const float* __restrict__ query,
             const float* __restrict__ key_b, const float* __restrict__ value_b,
             const float* __restrict__ d1W, const float* __restrict__ d1b,
             const float* __restrict__ d2W, const float* __restrict__ d2b,
             const float* __restrict__ d3W, const float* __restrict__ d3b,
             const float* __restrict__ scale_p, float* __restrict__ out)
{
    extern __shared__ float sm[];
    float* sWall = sm;
    float* sA    = sm + WALL_SZ;
    float* sD1   = sA + SA_SZ;
    float* sD2   = sD1 + 64 * 64;
    float* sD3   = sD2 + 64 * 32;

    const int tid = threadIdx.x;
    const int ct  = tid & 15;     // col-group: cols [4ct, 4ct+4)
    const int tt  = tid >> 4;     // token-group: tokens [8tt, 8tt+8)
    const int c0  = 4 * ct;
    const int t0  = 8 * tt;

    // ---- one-time weight staging into smem ----
    for (int i = tid; i < 64 * 640; i += THREADS) sWall[i] = g_Wall[i];
    for (int i = tid; i < 64 * 64;  i += THREADS) sD1[i] = d1W[i];
    for (int i = tid; i < 64 * 32;  i += THREADS) sD2[i] = d2W[i];
    for (int i = tid; i < 32 * 64;  i += THREADS) sD3[i] = d3W[i];

    const float scale = __ldg(scale_p);
    float kb[4], vb[4], b3v[4];
#pragma unroll
    for (int i = 0; i < 4; i++) {
        kb[i]  = __ldg(key_b   + c0 + i);
        vb[i]  = __ldg(value_b + c0 + i);
        b3v[i] = __ldg(d3b     + c0 + i);
    }
    u64 b1p0 = pack2(__ldg(d1b + c0),     __ldg(d1b + c0 + 1));
    u64 b1p1 = pack2(__ldg(d1b + c0 + 2), __ldg(d1b + c0 + 3));
    u64 b2p  = pack2(__ldg(d2b + 2 * ct), __ldg(d2b + 2 * ct + 1));
    u64 b3p0 = pack2(b3v[0], b3v[1]);
    u64 b3p1 = pack2(b3v[2], b3v[3]);

    const int tile0 = blockIdx.x;

    // ---- prologue prefetch: tile0's kv into registers ----
    float4 pk[8];
    {
        const int base = tile0 * TM;
#pragma unroll
        for (int r = 0; r < 8; r++) {
            int q4 = tid + r * THREADS;
            int t  = q4 >> 4;
            int j4 = (q4 & 15) << 2;
            pk[r] = *reinterpret_cast<const float4*>(kv_in + (size_t)(base + t) * 64 + j4);
        }
    }

    for (int tile = tile0; tile < NTILES; tile += GRID) {
        const int base = tile * TM;

        __syncthreads();   // sA free (prev tile's MLP3 reads done / staging done)
        // ---- commit prefetched kv, token-major: sA[t][ch] ----
#pragma unroll
        for (int r = 0; r < 8; r++) {
            int q4 = tid + r * THREADS;
            int t  = q4 >> 4;
            int j4 = (q4 & 15) << 2;
            *reinterpret_cast<float4*>(sA + t * SA_STRIDE + j4) = pk[r];
        }
        // ---- load this thread's 8 tokens x 7 query coeffs (56 contiguous floats) ----
        float qf[56];
        {
            const float* qp = query + (size_t)(base + t0) * 7;
#pragma unroll
            for (int r = 0; r < 14; r++) {
                float4 d = *reinterpret_cast<const float4*>(qp + 4 * r);
                qf[4 * r + 0] = d.x; qf[4 * r + 1] = d.y;
                qf[4 * r + 2] = d.z; qf[4 * r + 3] = d.w;
            }
        }
        __syncthreads();

        // ---- GEMM loop 1: hypernetwork fold  q_out = kv @ (Tb_re + sum_p q_p TW_p_re) ----
        u64 xx[8][2];
#pragma unroll
        for (int u = 0; u < 8; u++) { xx[u][0] = 0; xx[u][1] = 0; }

#pragma unroll 1
        for (int j = 0; j < 64; j++) {
            float a_[8];
#pragma unroll
            for (int u = 0; u < 8; u++) a_[u] = sA[(t0 + u) * SA_STRIDE + j];
            const float* wrow = sWall + j * 640 + c0;
            ulonglong2 bu0 = *reinterpret_cast<const ulonglong2*>(wrow + 2 * 64);
            ulonglong2 bu1 = *reinterpret_cast<const ulonglong2*>(wrow + 3 * 64);
            ulonglong2 bu2 = *reinterpret_cast<const ulonglong2*>(wrow + 4 * 64);
            ulonglong2 bu3 = *reinterpret_cast<const ulonglong2*>(wrow + 5 * 64);
            ulonglong2 bu4 = *reinterpret_cast<const ulonglong2*>(wrow + 6 * 64);
            ulonglong2 bu5 = *reinterpret_cast<const ulonglong2*>(wrow + 7 * 64);
            ulonglong2 bu6 = *reinterpret_cast<const ulonglong2*>(wrow + 8 * 64);
            ulonglong2 bb  = *reinterpret_cast<const ulonglong2*>(wrow + 9 * 64);
#pragma unroll
            for (int u = 0; u < 8; u++) {
                u64 w0 = bb.x, w1 = bb.y;
                u64 qp;
                qp = pack2(qf[u*7+0], qf[u*7+0]); w0 = ffma2(qp, bu0.x, w0); w1 = ffma2(qp, bu0.y, w1);
                qp = pack2(qf[u*7+1], qf[u*7+1]); w0 = ffma2(qp, bu1.x, w0); w1 = ffma2(qp, bu1.y, w1);
                qp = pack2(qf[u*7+2], qf[u*7+2]); w0 = ffma2(qp, bu2.x, w0); w1 = ffma2(qp, bu2.y, w1);
                qp = pack2(qf[u*7+3], qf[u*7+3]); w0 = ffma2(qp, bu3.x, w0); w1 = ffma2(qp, bu3.y, w1);
                qp = pack2(qf[u*7+4], qf[u*7+4]); w0 = ffma2(qp, bu4.x, w0); w1 = ffma2(qp, bu4.y, w1);
                qp = pack2(qf[u*7+5], qf[u*7+5]); w0 = ffma2(qp, bu5.x, w0); w1 = ffma2(qp, bu5.y, w1);
                qp = pack2(qf[u*7+6], qf[u*7+6]); w0 = ffma2(qp, bu6.x, w0); w1 = ffma2(qp, bu6.y, w1);
                u64 a2 = pack2(a_[u], a_[u]);
                xx[u][0] = ffma2(a2, w0, xx[u][0]);
                xx[u][1] = ffma2(a2, w1, xx[u][1]);
            }
        }

        // ---- GEMM loop 2: k and v projections ----
        u64 xk[8][2], xv[8][2];
#pragma unroll
        for (int u = 0; u < 8; u++) { xk[u][0]=0; xk[u][1]=0; xv[u][0]=0; xv[u][1]=0; }

#pragma unroll 2
        for (int j = 0; j < 64; j++) {
            float a_[8];
#pragma unroll
            for (int u = 0; u < 8; u++) a_[u] = sA[(t0 + u) * SA_STRIDE + j];
            const float* wrow = sWall + j * 640 + c0;
            ulonglong2 bk  = *reinterpret_cast<const ulonglong2*>(wrow);
            ulonglong2 bvv = *reinterpret_cast<const ulonglong2*>(wrow + 64);
#pragma unroll
            for (int u = 0; u < 8; u++) {
                u64 a2 = pack2(a_[u], a_[u]);
                xk[u][0] = ffma2(a2, bk.x,  xk[u][0]);
                xk[u][1] = ffma2(a2, bk.y,  xk[u][1]);
                xv[u][0] = ffma2(a2, bvv.x, xv[u][0]);
                xv[u][1] = ffma2(a2, bvv.y, xv[u][1]);
            }
        }

        // ---- epilogue per token: normalize(q*k) * softmax(v*scale), 16-lane shfl ----
        // (softmax computed without max-subtraction: args are bounded, mathematically identical)
#pragma unroll
        for (int u = 0; u < 8; u++) {
            float qv[4], kk[4], vv[4];
            unpack2(xx[u][0], qv[0], qv[1]); unpack2(xx[u][1], qv[2], qv[3]);
            unpack2(xk[u][0], kk[0], kk[1]); unpack2(xk[u][1], kk[2], kk[3]);
            unpack2(xv[u][0], vv[0], vv[1]); unpack2(xv[u][1], vv[2], vv[3]);

            float att[4], sv[4];
            float ss = 0.f, es = 0.f;
#pragma unroll
            for (int i = 0; i < 4; i++) {
                att[i] = qv[i] * (kk[i] + kb[i]);
                ss += att[i] * att[i];
                sv[i] = __expf((vv[i] + vb[i]) * scale);
                es += sv[i];
            }
            ss += __shfl_xor_sync(0xffffffffu, ss, 1);
            ss += __shfl_xor_sync(0xffffffffu, ss, 2);
            ss += __shfl_xor_sync(0xffffffffu, ss, 4);
            ss += __shfl_xor_sync(0xffffffffu, ss, 8);
            es += __shfl_xor_sync(0xffffffffu, es, 1);
            es += __shfl_xor_sync(0xffffffffu, es, 2);
            es += __shfl_xor_sync(0xffffffffu, es, 4);
            es += __shfl_xor_sync(0xffffffffu, es, 8);
            float inv_n = 1.0f / fmaxf(sqrtf(ss), 1e-8f);
            float inv_e = 1.0f / es;
            float s = inv_n * inv_e;
            // stash x back into xx (packed)
            xx[u][0] = pack2(att[0] * sv[0] * s, att[1] * sv[1] * s);
            xx[u][1] = pack2(att[2] * sv[2] * s, att[3] * sv[3] * s);
        }

        __syncthreads();   // all GEMM reads of kv done -> overwrite sA with x
#pragma unroll
        for (int u = 0; u < 8; u++) {
            float x0, x1, x2, x3;
            unpack2(xx[u][0], x0, x1); unpack2(xx[u][1], x2, x3);
            *reinterpret_cast<float4*>(sA + (t0 + u) * SA_STRIDE + c0) =
                make_float4(x0, x1, x2, x3);
        }
        __syncthreads();

        // ---- prefetch NEXT tile's kv (hidden under MLP phases) ----
        {
            int nt = tile + GRID;
            int pbase = (nt < NTILES ? nt : tile0) * TM;
#pragma unroll
            for (int r = 0; r < 8; r++) {
                int q4 = tid + r * THREADS;
                int t  = q4 >> 4;
                int j4 = (q4 & 15) << 2;
                pk[r] = *reinterpret_cast<const float4*>(kv_in + (size_t)(pbase + t) * 64 + j4);
            }
        }

        // ---- MLP1: h1 = relu(x @ d1 + b1), accumulate fully in regs ----
        u64 h1[8][2];
#pragma unroll
        for (int u = 0; u < 8; u++) { h1[u][0] = b1p0; h1[u][1] = b1p1; }
#pragma unroll 4
        for (int j = 0; j < 64; j++) {
            ulonglong2 bw = *reinterpret_cast<const ulonglong2*>(sD1 + j * 64 + c0);
#pragma unroll
            for (int u = 0; u < 8; u++) {
                float a = sA[(t0 + u) * SA_STRIDE + j];
                u64 a2 = pack2(a, a);
                h1[u][0] = ffma2(a2, bw.x, h1[u][0]);
                h1[u][1] = ffma2(a2, bw.y, h1[u][1]);
            }
        }
        __syncthreads();   // all x reads done
#pragma unroll
        for (int u = 0; u < 8; u++) {
            float h0, h1f, h2f, h3;
            unpack2(h1[u][0], h0, h1f); unpack2(h1[u][1], h2f, h3);
            *reinterpret_cast<float4*>(sA + (t0 + u) * SA_STRIDE + c0) =
                make_float4(fmaxf(h0, 0.f), fmaxf(h1f, 0.f), fmaxf(h2f, 0.f), fmaxf(h3, 0.f));
        }
        __syncthreads();

        // ---- MLP2: h2 = relu(h1 @ d2 + b2), cols {2ct, 2ct+1} ----
        u64 g2[8];
#pragma unroll
        for (int u = 0; u < 8; u++) g2[u] = b2p;
#pragma unroll 4
        for (int j = 0; j < 64; j++) {
            u64 bw = *reinterpret_cast<const u64*>(sD2 + j * 32 + 2 * ct);
#pragma unroll
            for (int u = 0; u < 8; u++) {
                float a = sA[(t0 + u) * SA_STRIDE + j];
                g2[u] = ffma2(pack2(a, a), bw, g2[u]);
            }
        }
        __syncthreads();   // all h1 reads done
#pragma unroll
        for (int u = 0; u < 8; u++) {
            float g0, g1;
            unpack2(g2[u], g0, g1);
            *reinterpret_cast<float2*>(sA + (t0 + u) * SA_STRIDE + 2 * ct) =
                make_float2(fmaxf(g0, 0.f), fmaxf(g1, 0.f));
        }
        __syncthreads();

        // ---- MLP3: out = h2 @ d3 + b3 ----
        u64 o2[8][2];
#pragma unroll
        for (int u = 0; u < 8; u++) { o2[u][0] = b3p0; o2[u][1] = b3p1; }
#pragma unroll 4
        for (int j = 0; j < 32; j++) {
            ulonglong2 bw = *reinterpret_cast<const ulonglong2*>(sD3 + j * 64 + c0);
#pragma unroll
            for (int u = 0; u < 8; u++) {
                float a = sA[(t0 + u) * SA_STRIDE + j];
                u64 a2 = pack2(a, a);
                o2[u][0] = ffma2(a2, bw.x, o2[u][0]);
                o2[u][1] = ffma2(a2, bw.y, o2[u][1]);
            }
        }
#pragma unroll
        for (int u = 0; u < 8; u++) {
            float o0, o1, o2f, o3;
            unpack2(o2[u][0], o0, o1); unpack2(o2[u][1], o2f, o3);
            *reinterpret_cast<float4*>(out + (size_t)(base + t0 + u) * 64 + c0) =
                make_float4(o0, o1, o2f, o3);
        }
    }
}

extern "C" void kernel_launch(void* const* d_in, const int* in_sizes, int n_in,
                              void* d_out, int out_size) {
    const float* kv      = (const float*)d_in[0];
    const float* query   = (const float*)d_in[1];
    const float* keyW    = (const float*)d_in[2];
    const float* keyb    = (const float*)d_in[3];
    const float* valW    = (const float*)d_in[4];
    const float* valb    = (const float*)d_in[5];
    const float* TW      = (const float*)d_in[6];
    const float* Tb      = (const float*)d_in[7];
    const float* d1W     = (const float*)d_in[8];
    const float* d1b     = (const float*)d_in[9];
    const float* d2W     = (const float*)d_in[10];
    const float* d2b     = (const float*)d_in[11];
    const float* d3W     = (const float*)d_in[12];
    const float* d3b     = (const float*)d_in[13];
    const float* scale   = (const float*)d_in[14];
    float* out           = (float*)d_out;

    cudaFuncSetAttribute(fused_kernel, cudaFuncAttributeMaxDynamicSharedMemorySize, SMEM_BYTES);

    prep_kernel<<<160, 256>>>(keyW, valW, TW, Tb);
    fused_kernel<<<GRID, THREADS, SMEM_BYTES>>>(kv, query, keyb, valb,
                                                d1W, d1b, d2W, d2b, d3W, d3b,
                                                scale, out);
}

// round 13
// speedup vs baseline: 1.5363x; 1.5363x over previous
#include <cuda_runtime.h>
#include <cstddef>

#define N_TOKENS 131072
#define TM 128
#define NTILES (N_TOKENS / TM)     // 1024
#define THREADS 256
#define GRID 148

// ---- shared memory layout (floats) ----
// Wall 64x640 | sA 64 ch x 132 (channel-major, reused kv->x->h1->h2) | D1 | D2 | D3
#define WALL_SZ   (64 * 640)       // 40960
#define SA_STRIDE 132
#define SA_SZ     (64 * SA_STRIDE) // 8448
#define SMEM_FLOATS (WALL_SZ + SA_SZ + 64*64 + 64*32 + 32*64)
#define SMEM_BYTES (SMEM_FLOATS * 4)   // 230400 B < 232448 limit

typedef unsigned long long u64;

__device__ __forceinline__ u64 pack2(float lo, float hi) {
    u64 r; asm("mov.b64 %0, {%1, %2};" : "=l"(r) : "f"(lo), "f"(hi)); return r;
}
__device__ __forceinline__ void unpack2(u64 v, float& lo, float& hi) {
    asm("mov.b64 {%0, %1}, %2;" : "=f"(lo), "=f"(hi) : "l"(v));
}
__device__ __forceinline__ u64 ffma2(u64 a, u64 b, u64 c) {
    u64 d; asm("fma.rn.f32x2 %0, %1, %2, %3;" : "=l"(d) : "l"(a), "l"(b), "l"(c)); return d;
}

// Packed weight matrix Wall[64 j][640 c], built per-launch by prep kernel.
// c in [0,64): key_W ; [64,128): value_W ; [128,576): T_W (p-major, i minor) ; [576,640): T_b
__device__ float g_Wall[64 * 640];

__global__ void prep_kernel(const float* __restrict__ keyW, const float* __restrict__ valW,
                            const float* __restrict__ TW,   const float* __restrict__ Tb) {
    int idx = blockIdx.x * blockDim.x + threadIdx.x;
    if (idx >= 64 * 640) return;
    int j = idx / 640;
    int c = idx % 640;
    float w;
    if (c < 64)       w = keyW[j * 64 + c];
    else if (c < 128) w = valW[j * 64 + (c - 64)];
    else if (c < 576) { int p = (c - 128) >> 6; int i = c & 63; w = TW[p * 4096 + i * 64 + j]; }
    else              { int i = c - 576;                        w = Tb[i * 64 + j]; }
    g_Wall[idx] = w;
}

__global__ void __launch_bounds__(THREADS, 1)
fused_kernel(const float* __restrict__ kv_in, const float* __restrict__ query,
             const float* __restrict__ key_b, const float* __restrict__ value_b,
             const float* __restrict__ d1W, const float* __restrict__ d1b,
             const float* __restrict__ d2W, const float* __restrict__ d2b,
             const float* __restrict__ d3W, const float* __restrict__ d3b,
             const float* __restrict__ scale_p, float* __restrict__ out)
{
    extern __shared__ float sm[];
    float* sWall = sm;
    float* sA    = sm + WALL_SZ;          // channel-major [64 ch][132]
    float* sD1   = sA + SA_SZ;
    float* sD2   = sD1 + 64 * 64;
    float* sD3   = sD2 + 64 * 32;

    const int tid = threadIdx.x;
    const int ct  = tid & 15;     // col-group: cols [4ct, 4ct+4)
    const int tt  = tid >> 4;     // token-group: tokens [8tt, 8tt+8)
    const int c0  = 4 * ct;
    const int t0  = 8 * tt;

    // ---- one-time weight staging into smem ----
    for (int i = tid; i < 64 * 640; i += THREADS) sWall[i] = g_Wall[i];
    for (int i = tid; i < 64 * 64;  i += THREADS) sD1[i] = d1W[i];
    for (int i = tid; i < 64 * 32;  i += THREADS) sD2[i] = d2W[i];
    for (int i = tid; i < 32 * 64;  i += THREADS) sD3[i] = d3W[i];

    const float scale = __ldg(scale_p);
    float kb[4], vb[4], b3v[4];
#pragma unroll
    for (int i = 0; i < 4; i++) {
        kb[i]  = __ldg(key_b   + c0 + i);
        vb[i]  = __ldg(value_b + c0 + i);
        b3v[i] = __ldg(d3b     + c0 + i);
    }
    u64 b1p0 = pack2(__ldg(d1b + c0),     __ldg(d1b + c0 + 1));
    u64 b1p1 = pack2(__ldg(d1b + c0 + 2), __ldg(d1b + c0 + 3));
    u64 b2p  = pack2(__ldg(d2b + 2 * ct), __ldg(d2b + 2 * ct + 1));
    u64 b3p0 = pack2(b3v[0], b3v[1]);
    u64 b3p1 = pack2(b3v[2], b3v[3]);

    const int tile0 = blockIdx.x;

    // ---- prologue prefetch: tile0's kv into registers ----
    float4 pk[8];
    {
        const int base = tile0 * TM;
#pragma unroll
        for (int r = 0; r < 8; r++) {
            int q4 = tid + r * THREADS;
            int t  = q4 >> 4;
            int j4 = (q4 & 15) << 2;
            pk[r] = *reinterpret_cast<const float4*>(kv_in + (size_t)(base + t) * 64 + j4);
        }
    }

    for (int tile = tile0; tile < NTILES; tile += GRID) {
        const int base = tile * TM;

        __syncthreads();   // sA free (prev tile's MLP3 reads done / staging done)

        // issue query loads early (latency covered by commit + sync)
        float4 pq[14];
        {
            const float* qp = query + (size_t)(base + t0) * 7;
#pragma unroll
            for (int r = 0; r < 14; r++)
                pq[r] = *reinterpret_cast<const float4*>(qp + 4 * r);
        }

        // ---- commit prefetched kv, channel-major: sA[ch][tok] ----
#pragma unroll
        for (int r = 0; r < 8; r++) {
            int q4 = tid + r * THREADS;
            int t  = q4 >> 4;
            int j4 = (q4 & 15) << 2;
            sA[(j4 + 0) * SA_STRIDE + t] = pk[r].x;
            sA[(j4 + 1) * SA_STRIDE + t] = pk[r].y;
            sA[(j4 + 2) * SA_STRIDE + t] = pk[r].z;
            sA[(j4 + 3) * SA_STRIDE + t] = pk[r].w;
        }

        // pack query coeffs ONCE per tile: qp2[tok][p] broadcast pairs (112 regs)
        u64 qp2[8][7];
        {
            float qf[56];
#pragma unroll
            for (int r = 0; r < 14; r++) {
                qf[4 * r + 0] = pq[r].x; qf[4 * r + 1] = pq[r].y;
                qf[4 * r + 2] = pq[r].z; qf[4 * r + 3] = pq[r].w;
            }
#pragma unroll
            for (int u = 0; u < 8; u++)
#pragma unroll
                for (int p = 0; p < 7; p++) {
                    float q = qf[u * 7 + p];
                    qp2[u][p] = pack2(q, q);
                }
        }
        __syncthreads();

        // ---- GEMM pass 1: hypernetwork fold (qp2 hoisted, dies at end of pass) ----
        u64 xx[8][2];
#pragma unroll
        for (int u = 0; u < 8; u++) { xx[u][0] = 0; xx[u][1] = 0; }

#pragma unroll 1
        for (int j = 0; j < 64; j++) {
            float4 avA = *reinterpret_cast<const float4*>(sA + j * SA_STRIDE + t0);
            float4 avB = *reinterpret_cast<const float4*>(sA + j * SA_STRIDE + t0 + 4);
            float a_[8] = {avA.x, avA.y, avA.z, avA.w, avB.x, avB.y, avB.z, avB.w};
            const float* wrow = sWall + j * 640 + c0;
            ulonglong2 bu0 = *reinterpret_cast<const ulonglong2*>(wrow + 2 * 64);
            ulonglong2 bu1 = *reinterpret_cast<const ulonglong2*>(wrow + 3 * 64);
            ulonglong2 bu2 = *reinterpret_cast<const ulonglong2*>(wrow + 4 * 64);
            ulonglong2 bu3 = *reinterpret_cast<const ulonglong2*>(wrow + 5 * 64);
            ulonglong2 bu4 = *reinterpret_cast<const ulonglong2*>(wrow + 6 * 64);
            ulonglong2 bu5 = *reinterpret_cast<const ulonglong2*>(wrow + 7 * 64);
            ulonglong2 bu6 = *reinterpret_cast<const ulonglong2*>(wrow + 8 * 64);
            ulonglong2 bb  = *reinterpret_cast<const ulonglong2*>(wrow + 9 * 64);
#pragma unroll
            for (int u = 0; u < 8; u++) {
                u64 w0 = bb.x, w1 = bb.y;
                w0 = ffma2(qp2[u][0], bu0.x, w0); w1 = ffma2(qp2[u][0], bu0.y, w1);
                w0 = ffma2(qp2[u][1], bu1.x, w0); w1 = ffma2(qp2[u][1], bu1.y, w1);
                w0 = ffma2(qp2[u][2], bu2.x, w0); w1 = ffma2(qp2[u][2], bu2.y, w1);
                w0 = ffma2(qp2[u][3], bu3.x, w0); w1 = ffma2(qp2[u][3], bu3.y, w1);
                w0 = ffma2(qp2[u][4], bu4.x, w0); w1 = ffma2(qp2[u][4], bu4.y, w1);
                w0 = ffma2(qp2[u][5], bu5.x, w0); w1 = ffma2(qp2[u][5], bu5.y, w1);
                w0 = ffma2(qp2[u][6], bu6.x, w0); w1 = ffma2(qp2[u][6], bu6.y, w1);
                u64 a2 = pack2(a_[u], a_[u]);
                xx[u][0] = ffma2(a2, w0, xx[u][0]);
                xx[u][1] = ffma2(a2, w1, xx[u][1]);
            }
        }

        // ---- GEMM pass 2: k and v projections (low register pressure) ----
        u64 xk[8][2], xv[8][2];
#pragma unroll
        for (int u = 0; u < 8; u++) { xk[u][0]=0; xk[u][1]=0; xv[u][0]=0; xv[u][1]=0; }

#pragma unroll 2
        for (int j = 0; j < 64; j++) {
            float4 avA = *reinterpret_cast<const float4*>(sA + j * SA_STRIDE + t0);
            float4 avB = *reinterpret_cast<const float4*>(sA + j * SA_STRIDE + t0 + 4);
            float a_[8] = {avA.x, avA.y, avA.z, avA.w, avB.x, avB.y, avB.z, avB.w};
            const float* wrow = sWall + j * 640 + c0;
            ulonglong2 bk  = *reinterpret_cast<const ulonglong2*>(wrow);
            ulonglong2 bvv = *reinterpret_cast<const ulonglong2*>(wrow + 64);
#pragma unroll
            for (int u = 0; u < 8; u++) {
                u64 a2 = pack2(a_[u], a_[u]);
                xk[u][0] = ffma2(a2, bk.x,  xk[u][0]);
                xk[u][1] = ffma2(a2, bk.y,  xk[u][1]);
                xv[u][0] = ffma2(a2, bvv.x, xv[u][0]);
                xv[u][1] = ffma2(a2, bvv.y, xv[u][1]);
            }
        }

        // ---- epilogue per token: normalize(q*k) * softmax(v*scale), 16-lane shfl ----
        // (no max-subtraction: bounded args, mathematically identical)
#pragma unroll
        for (int u = 0; u < 8; u++) {
            float qv[4], kk[4], vv[4];
            unpack2(xx[u][0], qv[0], qv[1]); unpack2(xx[u][1], qv[2], qv[3]);
            unpack2(xk[u][0], kk[0], kk[1]); unpack2(xk[u][1], kk[2], kk[3]);
            unpack2(xv[u][0], vv[0], vv[1]); unpack2(xv[u][1], vv[2], vv[3]);

            float att[4], sv[4];
            float ss = 0.f, es = 0.f;
#pragma unroll
            for (int i = 0; i < 4; i++) {
                att[i] = qv[i] * (kk[i] + kb[i]);
                ss += att[i] * att[i];
                sv[i] = __expf((vv[i] + vb[i]) * scale);
                es += sv[i];
            }
            ss += __shfl_xor_sync(0xffffffffu, ss, 1);
            ss += __shfl_xor_sync(0xffffffffu, ss, 2);
            ss += __shfl_xor_sync(0xffffffffu, ss, 4);
            ss += __shfl_xor_sync(0xffffffffu, ss, 8);
            es += __shfl_xor_sync(0xffffffffu, es, 1);
            es += __shfl_xor_sync(0xffffffffu, es, 2);
            es += __shfl_xor_sync(0xffffffffu, es, 4);
            es += __shfl_xor_sync(0xffffffffu, es, 8);
            float inv_n = 1.0f / fmaxf(sqrtf(ss), 1e-8f);
            float s = inv_n / es;
            xx[u][0] = pack2(att[0] * sv[0] * s, att[1] * sv[1] * s);
            xx[u][1] = pack2(att[2] * sv[2] * s, att[3] * sv[3] * s);
        }

        __syncthreads();   // all GEMM reads of kv done -> overwrite sA with x
        // write x channel-major: per channel c0+i, 8 token values = 2 float4
#pragma unroll
        for (int h = 0; h < 2; h++) {   // h: 0 -> cols c0,c0+1 ; 1 -> c0+2,c0+3
            float lo0, hi0, lo1, hi1, lo2, hi2, lo3, hi3;
            unpack2(xx[0][h], lo0, hi0); unpack2(xx[1][h], lo1, hi1);
            unpack2(xx[2][h], lo2, hi2); unpack2(xx[3][h], lo3, hi3);
            float lo4, hi4, lo5, hi5, lo6, hi6, lo7, hi7;
            unpack2(xx[4][h], lo4, hi4); unpack2(xx[5][h], lo5, hi5);
            unpack2(xx[6][h], lo6, hi6); unpack2(xx[7][h], lo7, hi7);
            *reinterpret_cast<float4*>(sA + (c0 + 2*h)     * SA_STRIDE + t0)     = make_float4(lo0, lo1, lo2, lo3);
            *reinterpret_cast<float4*>(sA + (c0 + 2*h)     * SA_STRIDE + t0 + 4) = make_float4(lo4, lo5, lo6, lo7);
            *reinterpret_cast<float4*>(sA + (c0 + 2*h + 1) * SA_STRIDE + t0)     = make_float4(hi0, hi1, hi2, hi3);
            *reinterpret_cast<float4*>(sA + (c0 + 2*h + 1) * SA_STRIDE + t0 + 4) = make_float4(hi4, hi5, hi6, hi7);
        }
        __syncthreads();

        // ---- prefetch NEXT tile's kv (hidden under MLP phases) ----
        {
            int nt = tile + GRID;
            int pbase = (nt < NTILES ? nt : tile0) * TM;
#pragma unroll
            for (int r = 0; r < 8; r++) {
                int q4 = tid + r * THREADS;
                int t  = q4 >> 4;
                int j4 = (q4 & 15) << 2;
                pk[r] = *reinterpret_cast<const float4*>(kv_in + (size_t)(pbase + t) * 64 + j4);
            }
        }

        // ---- MLP1: h1 = relu(x @ d1 + b1), accumulate in regs, in-place ----
        u64 h1[8][2];
#pragma unroll
        for (int u = 0; u < 8; u++) { h1[u][0] = b1p0; h1[u][1] = b1p1; }
#pragma unroll 4
        for (int j = 0; j < 64; j++) {
            float4 avA = *reinterpret_cast<const float4*>(sA + j * SA_STRIDE + t0);
            float4 avB = *reinterpret_cast<const float4*>(sA + j * SA_STRIDE + t0 + 4);
            float a_[8] = {avA.x, avA.y, avA.z, avA.w, avB.x, avB.y, avB.z, avB.w};
            ulonglong2 bw = *reinterpret_cast<const ulonglong2*>(sD1 + j * 64 + c0);
#pragma unroll
            for (int u = 0; u < 8; u++) {
                u64 a2 = pack2(a_[u], a_[u]);
                h1[u][0] = ffma2(a2, bw.x, h1[u][0]);
                h1[u][1] = ffma2(a2, bw.y, h1[u][1]);
            }
        }
        __syncthreads();   // all x reads done
#pragma unroll
        for (int h = 0; h < 2; h++) {
            float v_[8][2];
#pragma unroll
            for (int u = 0; u < 8; u++) unpack2(h1[u][h], v_[u][0], v_[u][1]);
#pragma unroll
            for (int s = 0; s < 2; s++) {
                *reinterpret_cast<float4*>(sA + (c0 + 2*h + s) * SA_STRIDE + t0) =
                    make_float4(fmaxf(v_[0][s], 0.f), fmaxf(v_[1][s], 0.f),
                                fmaxf(v_[2][s], 0.f), fmaxf(v_[3][s], 0.f));
                *reinterpret_cast<float4*>(sA + (c0 + 2*h + s) * SA_STRIDE + t0 + 4) =
                    make_float4(fmaxf(v_[4][s], 0.f), fmaxf(v_[5][s], 0.f),
                                fmaxf(v_[6][s], 0.f), fmaxf(v_[7][s], 0.f));
            }
        }
        __syncthreads();

        // ---- MLP2: h2 = relu(h1 @ d2 + b2), cols {2ct, 2ct+1} ----
        u64 g2[8];
#pragma unroll
        for (int u = 0; u < 8; u++) g2[u] = b2p;
#pragma unroll 4
        for (int j = 0; j < 64; j++) {
            float4 avA = *reinterpret_cast<const float4*>(sA + j * SA_STRIDE + t0);
            float4 avB = *reinterpret_cast<const float4*>(sA + j * SA_STRIDE + t0 + 4);
            float a_[8] = {avA.x, avA.y, avA.z, avA.w, avB.x, avB.y, avB.z, avB.w};
            u64 bw = *reinterpret_cast<const u64*>(sD2 + j * 32 + 2 * ct);
#pragma unroll
            for (int u = 0; u < 8; u++)
                g2[u] = ffma2(pack2(a_[u], a_[u]), bw, g2[u]);
        }
        __syncthreads();   // all h1 reads done
        {
            float v_[8][2];
#pragma unroll
            for (int u = 0; u < 8; u++) unpack2(g2[u], v_[u][0], v_[u][1]);
#pragma unroll
            for (int s = 0; s < 2; s++) {
                *reinterpret_cast<float4*>(sA + (2 * ct + s) * SA_STRIDE + t0) =
                    make_float4(fmaxf(v_[0][s], 0.f), fmaxf(v_[1][s], 0.f),
                                fmaxf(v_[2][s], 0.f), fmaxf(v_[3][s], 0.f));
                *reinterpret_cast<float4*>(sA + (2 * ct + s) * SA_STRIDE + t0 + 4) =
                    make_float4(fmaxf(v_[4][s], 0.f), fmaxf(v_[5][s], 0.f),
                                fmaxf(v_[6][s], 0.f), fmaxf(v_[7][s], 0.f));
            }
        }
        __syncthreads();

        // ---- MLP3: out = h2 @ d3 + b3 ----
        u64 o2[8][2];
#pragma unroll
        for (int u = 0; u < 8; u++) { o2[u][0] = b3p0; o2[u][1] = b3p1; }
#pragma unroll 4
        for (int j = 0; j < 32; j++) {
            float4 avA = *reinterpret_cast<const float4*>(sA + j * SA_STRIDE + t0);
            float4 avB = *reinterpret_cast<const float4*>(sA + j * SA_STRIDE + t0 + 4);
            float a_[8] = {avA.x, avA.y, avA.z, avA.w, avB.x, avB.y, avB.z, avB.w};
            ulonglong2 bw = *reinterpret_cast<const ulonglong2*>(sD3 + j * 64 + c0);
#pragma unroll
            for (int u = 0; u < 8; u++) {
                u64 a2 = pack2(a_[u], a_[u]);
                o2[u][0] = ffma2(a2, bw.x, o2[u][0]);
                o2[u][1] = ffma2(a2, bw.y, o2[u][1]);
            }
        }
#pragma unroll
        for (int u = 0; u < 8; u++) {
            float o0, o1, o2f, o3;
            unpack2(o2[u][0], o0, o1); unpack2(o2[u][1], o2f, o3);
            *reinterpret_cast<float4*>(out + (size_t)(base + t0 + u) * 64 + c0) =
                make_float4(o0, o1, o2f, o3);
        }
    }
}

extern "C" void kernel_launch(void* const* d_in, const int* in_sizes, int n_in,
                              void* d_out, int out_size) {
    const float* kv      = (const float*)d_in[0];
    const float* query   = (const float*)d_in[1];
    const float* keyW    = (const float*)d_in[2];
    const float* keyb    = (const float*)d_in[3];
    const float* valW    = (const float*)d_in[4];
    const float* valb    = (const float*)d_in[5];
    const float* TW      = (const float*)d_in[6];
    const float* Tb      = (const float*)d_in[7];
    const float* d1W     = (const float*)d_in[8];
    const float* d1b     = (const float*)d_in[9];
    const float* d2W     = (const float*)d_in[10];
    const float* d2b     = (const float*)d_in[11];
    const float* d3W     = (const float*)d_in[12];
    const float* d3b     = (const float*)d_in[13];
    const float* scale   = (const float*)d_in[14];
    float* out           = (float*)d_out;

    cudaFuncSetAttribute(fused_kernel, cudaFuncAttributeMaxDynamicSharedMemorySize, SMEM_BYTES);

    prep_kernel<<<160, 256>>>(keyW, valW, TW, Tb);
    fused_kernel<<<GRID, THREADS, SMEM_BYTES>>>(kv, query, keyb, valb,
                                                d1W, d1b, d2W, d2b, d3W, d3b,
                                                scale, out);
}

// round 16
// speedup vs baseline: 3.5447x; 2.3072x over previous
#include <cuda_runtime.h>
#include <cuda_fp16.h>
#include <cstdint>
#include <cstddef>

typedef unsigned long long u64;
typedef unsigned int u32;

#define N_TOKENS 131072
#define TM 128
#define NTILES (N_TOKENS / TM)   // 1024
#define THREADS 256
#define GRID 148
#define SEG_N 640

#define SW128(x) ((x) ^ (((x) >> 3) & 0x70))

// ---- smem layout (bytes) ----
#define SM_W   0                         // Wall f16 [640 n][64 k] swizzled   81920
#define SM_A   81920                     // kv f16  [128 t][64 k] swizzled    16384
#define SM_SA  98304                     // fp32 [64 ch][132] MLP buffer      33792
#define SM_D1  132096                    // 16384
#define SM_D2  148480                    //  8192
#define SM_D3  156672                    //  8192
#define SM_KB  164864                    //   256
#define SM_VB  165120                    //   256
#define SM_TOTAL 165376

__device__ __half g_Wf16[SEG_N * 64];    // [n][k], n = seg-major column

__global__ void prep_w_kernel(const float* __restrict__ keyW, const float* __restrict__ valW,
                              const float* __restrict__ TW,   const float* __restrict__ Tb) {
    int idx = blockIdx.x * blockDim.x + threadIdx.x;
    if (idx >= SEG_N * 64) return;
    int n = idx >> 6;
    int k = idx & 63;
    int seg = n >> 6;
    int ni  = n & 63;
    float w;
    if (seg == 0)      w = keyW[k * 64 + ni];
    else if (seg == 1) w = valW[k * 64 + ni];
    else if (seg <= 8) { int p = seg - 2; w = TW[p * 4096 + ni * 64 + k]; }
    else               w = Tb[ni * 64 + k];
    g_Wf16[idx] = __float2half_rn(w);
}

// ---- asm helpers ----
__device__ __forceinline__ u32 smem_u32(const void* p) {
    u32 a; asm("{ .reg .u64 t; cvta.to.shared.u64 t, %1; cvt.u32.u64 %0, t; }" : "=r"(a) : "l"(p));
    return a;
}
__device__ __forceinline__ void ldmx4(u32& r0, u32& r1, u32& r2, u32& r3, u32 addr) {
    asm volatile("ldmatrix.sync.aligned.m8n8.x4.shared.b16 {%0,%1,%2,%3}, [%4];"
                 : "=r"(r0), "=r"(r1), "=r"(r2), "=r"(r3) : "r"(addr));
}
__device__ __forceinline__ void mma16816(float* d, const u32* a, u32 b0, u32 b1) {
    asm volatile("mma.sync.aligned.m16n8k16.row.col.f32.f16.f16.f32 "
                 "{%0,%1,%2,%3}, {%4,%5,%6,%7}, {%8,%9}, {%0,%1,%2,%3};"
                 : "+f"(d[0]), "+f"(d[1]), "+f"(d[2]), "+f"(d[3])
                 : "r"(a[0]), "r"(a[1]), "r"(a[2]), "r"(a[3]), "r"(b0), "r"(b1));
}
__device__ __forceinline__ u64 pack2(float lo, float hi) {
    u64 r; asm("mov.b64 %0, {%1, %2};" : "=l"(r) : "f"(lo), "f"(hi)); return r;
}
__device__ __forceinline__ void unpack2(u64 v, float& lo, float& hi) {
    asm("mov.b64 {%0, %1}, %2;" : "=f"(lo), "=f"(hi) : "l"(v));
}
__device__ __forceinline__ u64 ffma2(u64 a, u64 b, u64 c) {
    u64 d; asm("fma.rn.f32x2 %0, %1, %2, %3;" : "=l"(d) : "l"(a), "l"(b), "l"(c)); return d;
}

// one 64-col segment GEMM: acc[f*4+j] += A(16 tok) x W[n0..n0+63]
__device__ __forceinline__ void gemm_seg(float* acc, int n0, const u32 a[4][4],
                                         u32 sWb, int lane) {
    const int rowb = n0 + (lane & 7);
    const u32 roff = (u32)((lane >> 3) * 16);   // 0/16/32/48 -> m0..m3 k-pieces
#pragma unroll
    for (int f = 0; f < 8; f++) {
        u32 base = (u32)((rowb + f * 8) * 128) + roff;
        u32 b0, b1, b2, b3, b4, b5, b6, b7;
        ldmx4(b0, b1, b2, b3, sWb + SW128(base));        // ksteps 0,1
        ldmx4(b4, b5, b6, b7, sWb + SW128(base + 64));   // ksteps 2,3
        mma16816(acc + f * 4, a[0], b0, b1);
        mma16816(acc + f * 4, a[1], b2, b3);
        mma16816(acc + f * 4, a[2], b4, b5);
        mma16816(acc + f * 4, a[3], b6, b7);
    }
}

__global__ void __launch_bounds__(THREADS, 1)
fused_kernel(const float* __restrict__ kv_in, const float* __restrict__ query,
             const float* __restrict__ key_b, const float* __restrict__ value_b,
             const float* __restrict__ d1W, const float* __restrict__ d1b,
             const float* __restrict__ d2W, const float* __restrict__ d2b,
             const float* __restrict__ d3W, const float* __restrict__ d3b,
             const float* __restrict__ scale_p, float* __restrict__ out)
{
    extern __shared__ char smem[];
    const u32 sWb  = smem_u32(smem) + SM_W;
    const u32 sAb  = smem_u32(smem) + SM_A;
    float* sAf = reinterpret_cast<float*>(smem + SM_SA);
    float* sD1 = reinterpret_cast<float*>(smem + SM_D1);
    float* sD2 = reinterpret_cast<float*>(smem + SM_D2);
    float* sD3 = reinterpret_cast<float*>(smem + SM_D3);
    float* sKB = reinterpret_cast<float*>(smem + SM_KB);
    float* sVB = reinterpret_cast<float*>(smem + SM_VB);

    const int tid  = threadIdx.x;
    const int lane = tid & 31;
    const int w    = tid >> 5;          // warp: tokens [16w, 16w+16)
    const int g    = lane >> 2;
    const int tg   = lane & 3;
    // MLP mapping (R13)
    const int ct = tid & 15;
    const int tt = tid >> 4;
    const int c0m = 4 * ct;
    const int t0m = 8 * tt;

    // ---- one-time staging ----
    for (int i = tid; i < 5120; i += THREADS) {           // Wall f16, swizzled
        int row = i >> 3, ch = i & 7;
        uint4 v = reinterpret_cast<const uint4*>(g_Wf16)[i];
        *reinterpret_cast<uint4*>(smem + SM_W + SW128(row * 128 + ch * 16)) = v;
    }
    for (int i = tid; i < 64 * 64; i += THREADS) sD1[i] = d1W[i];
    for (int i = tid; i < 64 * 32; i += THREADS) sD2[i] = d2W[i];
    for (int i = tid; i < 32 * 64; i += THREADS) sD3[i] = d3W[i];
    for (int i = tid; i < 64; i += THREADS) { sKB[i] = key_b[i]; sVB[i] = value_b[i]; }

    const float scale = __ldg(scale_p);
    float b3v[4];
#pragma unroll
    for (int i = 0; i < 4; i++) b3v[i] = __ldg(d3b + c0m + i);
    u64 b1p0 = pack2(__ldg(d1b + c0m),     __ldg(d1b + c0m + 1));
    u64 b1p1 = pack2(__ldg(d1b + c0m + 2), __ldg(d1b + c0m + 3));
    u64 b2p  = pack2(__ldg(d2b + 2 * ct),  __ldg(d2b + 2 * ct + 1));
    u64 b3p0 = pack2(b3v[0], b3v[1]);
    u64 b3p1 = pack2(b3v[2], b3v[3]);

    const int tile0 = blockIdx.x;

    // prologue kv prefetch
    float4 pk[8];
    {
        const int base = tile0 * TM;
#pragma unroll
        for (int r = 0; r < 8; r++) {
            int idx = tid + r * THREADS;
            int t = idx >> 4, j4 = (idx & 15) << 2;
            pk[r] = *reinterpret_cast<const float4*>(kv_in + (size_t)(base + t) * 64 + j4);
        }
    }

    for (int tile = tile0; tile < NTILES; tile += GRID) {
        const int base = tile * TM;

        __syncthreads();   // staging done / prev tile fully consumed

        // ---- commit kv -> f16 swizzled A ----
#pragma unroll
        for (int r = 0; r < 8; r++) {
            int idx = tid + r * THREADS;
            int t = idx >> 4, j4 = (idx & 15) << 2;
            __half2 h0 = __floats2half2_rn(pk[r].x, pk[r].y);
            __half2 h1 = __floats2half2_rn(pk[r].z, pk[r].w);
            uint2 o = make_uint2(*reinterpret_cast<u32*>(&h0), *reinterpret_cast<u32*>(&h1));
            *reinterpret_cast<uint2*>(smem + SM_A + SW128(t * 128 + j4 * 2)) = o;
        }

        // per-lane query coeffs for tokens T0 = 16w+g, T1 = T0+8  (c[7]=1 for Tb)
        float cA[8], cB[8];
        {
            const float* q0 = query + (size_t)(base + 16 * w + g) * 7;
            const float* q1 = q0 + 8 * 7;
#pragma unroll
            for (int p = 0; p < 7; p++) { cA[p] = __ldg(q0 + p); cB[p] = __ldg(q1 + p); }
            cA[7] = 1.f; cB[7] = 1.f;
        }
        __syncthreads();

        // ---- A fragments (once per tile, reused for all 10 segments) ----
        u32 a[4][4];
        {
            int rowa = w * 16 + (lane & 15);
            u32 aoff = (u32)(((lane >> 4) & 1) * 16);
#pragma unroll
            for (int k = 0; k < 4; k++)
                ldmx4(a[k][0], a[k][1], a[k][2], a[k][3],
                      sAb + SW128((u32)(rowa * 128) + (u32)(k * 32) + aoff));
        }

        // ---- segment GEMMs ----
        float accK[32], accV[32], accQ[32];
#pragma unroll
        for (int i = 0; i < 32; i++) { accK[i] = 0.f; accV[i] = 0.f; accQ[i] = 0.f; }
        gemm_seg(accK, 0,  a, sWb, lane);
        gemm_seg(accV, 64, a, sWb, lane);
#pragma unroll
        for (int si = 0; si < 8; si++) {          // U0..U6, Tb
            float accT[32];
#pragma unroll
            for (int i = 0; i < 32; i++) accT[i] = 0.f;
            gemm_seg(accT, 128 + si * 64, a, sWb, lane);
            float ca = cA[si], cb = cB[si];
#pragma unroll
            for (int f = 0; f < 8; f++) {
                accQ[f*4+0] += ca * accT[f*4+0];
                accQ[f*4+1] += ca * accT[f*4+1];
                accQ[f*4+2] += cb * accT[f*4+2];
                accQ[f*4+3] += cb * accT[f*4+3];
            }
        }

        // ---- epilogue in fragment layout ----
        // lane covers cols {8f+2tg, 8f+2tg+1}; rows T0 (j=0,1), T1 (j=2,3)
        float ss0 = 0.f, es0 = 0.f, ss1 = 0.f, es1 = 0.f;
#pragma unroll
        for (int f = 0; f < 8; f++) {
            int col = f * 8 + 2 * tg;
            float2 kb2 = *reinterpret_cast<const float2*>(sKB + col);
            float2 vb2 = *reinterpret_cast<const float2*>(sVB + col);
            float a0 = accQ[f*4+0] * (accK[f*4+0] + kb2.x);
            float a1 = accQ[f*4+1] * (accK[f*4+1] + kb2.y);
            float a2 = accQ[f*4+2] * (accK[f*4+2] + kb2.x);
            float a3 = accQ[f*4+3] * (accK[f*4+3] + kb2.y);
            ss0 += a0 * a0 + a1 * a1;
            ss1 += a2 * a2 + a3 * a3;
            float s0 = __expf((accV[f*4+0] + vb2.x) * scale);
            float s1 = __expf((accV[f*4+1] + vb2.y) * scale);
            float s2 = __expf((accV[f*4+2] + vb2.x) * scale);
            float s3 = __expf((accV[f*4+3] + vb2.y) * scale);
            es0 += s0 + s1; es1 += s2 + s3;
            accQ[f*4+0] = a0; accQ[f*4+1] = a1; accQ[f*4+2] = a2; accQ[f*4+3] = a3;
            accV[f*4+0] = s0; accV[f*4+1] = s1; accV[f*4+2] = s2; accV[f*4+3] = s3;
        }
        ss0 += __shfl_xor_sync(0xffffffffu, ss0, 1);
        ss0 += __shfl_xor_sync(0xffffffffu, ss0, 2);
        ss1 += __shfl_xor_sync(0xffffffffu, ss1, 1);
        ss1 += __shfl_xor_sync(0xffffffffu, ss1, 2);
        es0 += __shfl_xor_sync(0xffffffffu, es0, 1);
        es0 += __shfl_xor_sync(0xffffffffu, es0, 2);
        es1 += __shfl_xor_sync(0xffffffffu, es1, 1);
        es1 += __shfl_xor_sync(0xffffffffu, es1, 2);
        float sc0 = (1.0f / fmaxf(sqrtf(ss0), 1e-8f)) / es0;
        float sc1 = (1.0f / fmaxf(sqrtf(ss1), 1e-8f)) / es1;

        // x -> sA fp32 channel-major [col][132]
        {
            int T0l = 16 * w + g, T1l = T0l + 8;
#pragma unroll
            for (int f = 0; f < 8; f++) {
                int col = f * 8 + 2 * tg;
                sAf[col       * 132 + T0l] = accQ[f*4+0] * accV[f*4+0] * sc0;
                sAf[(col + 1) * 132 + T0l] = accQ[f*4+1] * accV[f*4+1] * sc0;
                sAf[col       * 132 + T1l] = accQ[f*4+2] * accV[f*4+2] * sc1;
                sAf[(col + 1) * 132 + T1l] = accQ[f*4+3] * accV[f*4+3] * sc1;
            }
        }
        __syncthreads();

        // ---- prefetch next tile kv ----
        {
            int nt = tile + GRID;
            int pbase = (nt < NTILES ? nt : tile0) * TM;
#pragma unroll
            for (int r = 0; r < 8; r++) {
                int idx = tid + r * THREADS;
                int t = idx >> 4, j4 = (idx & 15) << 2;
                pk[r] = *reinterpret_cast<const float4*>(kv_in + (size_t)(pbase + t) * 64 + j4);
            }
        }

        // ---- MLP1: h1 = relu(x @ d1 + b1)  (R13 machinery) ----
        u64 h1[8][2];
#pragma unroll
        for (int u = 0; u < 8; u++) { h1[u][0] = b1p0; h1[u][1] = b1p1; }
#pragma unroll 4
        for (int j = 0; j < 64; j++) {
            float4 avA = *reinterpret_cast<const float4*>(sAf + j * 132 + t0m);
            float4 avB = *reinterpret_cast<const float4*>(sAf + j * 132 + t0m + 4);
            float a_[8] = {avA.x, avA.y, avA.z, avA.w, avB.x, avB.y, avB.z, avB.w};
            ulonglong2 bw = *reinterpret_cast<const ulonglong2*>(sD1 + j * 64 + c0m);
#pragma unroll
            for (int u = 0; u < 8; u++) {
                u64 a2 = pack2(a_[u], a_[u]);
                h1[u][0] = ffma2(a2, bw.x, h1[u][0]);
                h1[u][1] = ffma2(a2, bw.y, h1[u][1]);
            }
        }
        __syncthreads();
#pragma unroll
        for (int h = 0; h < 2; h++) {
            float v_[8][2];
#pragma unroll
            for (int u = 0; u < 8; u++) unpack2(h1[u][h], v_[u][0], v_[u][1]);
#pragma unroll
            for (int s = 0; s < 2; s++) {
                *reinterpret_cast<float4*>(sAf + (c0m + 2*h + s) * 132 + t0m) =
                    make_float4(fmaxf(v_[0][s], 0.f), fmaxf(v_[1][s], 0.f),
                                fmaxf(v_[2][s], 0.f), fmaxf(v_[3][s], 0.f));
                *reinterpret_cast<float4*>(sAf + (c0m + 2*h + s) * 132 + t0m + 4) =
                    make_float4(fmaxf(v_[4][s], 0.f), fmaxf(v_[5][s], 0.f),
                                fmaxf(v_[6][s], 0.f), fmaxf(v_[7][s], 0.f));
            }
        }
        __syncthreads();

        // ---- MLP2 ----
        u64 g2[8];
#pragma unroll
        for (int u = 0; u < 8; u++) g2[u] = b2p;
#pragma unroll 4
        for (int j = 0; j < 64; j++) {
            float4 avA = *reinterpret_cast<const float4*>(sAf + j * 132 + t0m);
            float4 avB = *reinterpret_cast<const float4*>(sAf + j * 132 + t0m + 4);
            float a_[8] = {avA.x, avA.y, avA.z, avA.w, avB.x, avB.y, avB.z, avB.w};
            u64 bw = *reinterpret_cast<const u64*>(sD2 + j * 32 + 2 * ct);
#pragma unroll
            for (int u = 0; u < 8; u++)
                g2[u] = ffma2(pack2(a_[u], a_[u]), bw, g2[u]);
        }
        __syncthreads();
        {
            float v_[8][2];
#pragma unroll
            for (int u = 0; u < 8; u++) unpack2(g2[u], v_[u][0], v_[u][1]);
#pragma unroll
            for (int s = 0; s < 2; s++) {
                *reinterpret_cast<float4*>(sAf + (2 * ct + s) * 132 + t0m) =
                    make_float4(fmaxf(v_[0][s], 0.f), fmaxf(v_[1][s], 0.f),
                                fmaxf(v_[2][s], 0.f), fmaxf(v_[3][s], 0.f));
                *reinterpret_cast<float4*>(sAf + (2 * ct + s) * 132 + t0m + 4) =
                    make_float4(fmaxf(v_[4][s], 0.f), fmaxf(v_[5][s], 0.f),
                                fmaxf(v_[6][s], 0.f), fmaxf(v_[7][s], 0.f));
            }
        }
        __syncthreads();

        // ---- MLP3 ----
        u64 o2[8][2];
#pragma unroll
        for (int u = 0; u < 8; u++) { o2[u][0] = b3p0; o2[u][1] = b3p1; }
#pragma unroll 4
        for (int j = 0; j < 32; j++) {
            float4 avA = *reinterpret_cast<const float4*>(sAf + j * 132 + t0m);
            float4 avB = *reinterpret_cast<const float4*>(sAf + j * 132 + t0m + 4);
            float a_[8] = {avA.x, avA.y, avA.z, avA.w, avB.x, avB.y, avB.z, avB.w};
            ulonglong2 bw = *reinterpret_cast<const ulonglong2*>(sD3 + j * 64 + c0m);
#pragma unroll
            for (int u = 0; u < 8; u++) {
                u64 a2 = pack2(a_[u], a_[u]);
                o2[u][0] = ffma2(a2, bw.x, o2[u][0]);
                o2[u][1] = ffma2(a2, bw.y, o2[u][1]);
            }
        }
#pragma unroll
        for (int u = 0; u < 8; u++) {
            float o0, o1, o2f, o3;
            unpack2(o2[u][0], o0, o1); unpack2(o2[u][1], o2f, o3);
            *reinterpret_cast<float4*>(out + (size_t)(base + t0m + u) * 64 + c0m) =
                make_float4(o0, o1, o2f, o3);
        }
    }
}

extern "C" void kernel_launch(void* const* d_in, const int* in_sizes, int n_in,
                              void* d_out, int out_size) {
    const float* kv      = (const float*)d_in[0];
    const float* query   = (const float*)d_in[1];
    const float* keyW    = (const float*)d_in[2];
    const float* keyb    = (const float*)d_in[3];
    const float* valW    = (const float*)d_in[4];
    const float* valb    = (const float*)d_in[5];
    const float* TW      = (const float*)d_in[6];
    const float* Tb      = (const float*)d_in[7];
    const float* d1W     = (const float*)d_in[8];
    const float* d1b     = (const float*)d_in[9];
    const float* d2W     = (const float*)d_in[10];
    const float* d2b     = (const float*)d_in[11];
    const float* d3W     = (const float*)d_in[12];
    const float* d3b     = (const float*)d_in[13];
    const float* scale   = (const float*)d_in[14];
    float* out           = (float*)d_out;

    cudaFuncSetAttribute(fused_kernel, cudaFuncAttributeMaxDynamicSharedMemorySize, SM_TOTAL);

    prep_w_kernel<<<160, 256>>>(keyW, valW, TW, Tb);
    fused_kernel<<<GRID, THREADS, SM_TOTAL>>>(kv, query, keyb, valb,
                                              d1W, d1b, d2W, d2b, d3W, d3b,
                                              scale, out);
}

// round 17
// speedup vs baseline: 5.6969x; 1.6072x over previous
#include <cuda_runtime.h>
#include <cuda_fp16.h>
#include <cstdint>
#include <cstddef>

typedef unsigned long long u64;
typedef unsigned int u32;

#define N_TOKENS 131072
#define TM 128
#define NTILES (N_TOKENS / TM)   // 1024
#define THREADS 256
#define GRID 148
#define SEG_N 640

#define SW128(x) ((x) ^ (((x) >> 3) & 0x70))

// ---- smem layout (bytes, all swizzled regions 1024-aligned) ----
#define SM_W    0                      // Wall f16 [640][64]          81920
#define SM_A    81920                  // kv f16 [128][64]            16384
#define SM_XH   98304                  // act hi f16 [128][64]        16384
#define SM_XL   114688                 // act lo f16 [128][64]        16384
#define SM_D1H  131072                 // d1 hi [64][64]               8192
#define SM_D1L  139264
#define SM_D2H  147456                 // d2 hi [32][64]               4096
#define SM_D2L  151552
#define SM_D3H  155648                 // d3 hi [64][64 pad]           8192
#define SM_D3L  163840
#define SM_KB   172032                 // fp32 biases
#define SM_VB   172288
#define SM_B1   172544
#define SM_B2   172800
#define SM_B3   172928
#define SM_TOTAL 173184

__device__ __half g_Wf16[SEG_N * 64];
__device__ __half g_D1h[64 * 64], g_D1l[64 * 64];
__device__ __half g_D2h[32 * 64], g_D2l[32 * 64];
__device__ __half g_D3h[64 * 64], g_D3l[64 * 64];

__global__ void prep_kernel(const float* __restrict__ keyW, const float* __restrict__ valW,
                            const float* __restrict__ TW,   const float* __restrict__ Tb,
                            const float* __restrict__ d1W,  const float* __restrict__ d2W,
                            const float* __restrict__ d3W) {
    int idx = blockIdx.x * blockDim.x + threadIdx.x;
    if (idx < SEG_N * 64) {
        int n = idx >> 6, k = idx & 63;
        int seg = n >> 6, ni = n & 63;
        float w;
        if (seg == 0)      w = keyW[k * 64 + ni];
        else if (seg == 1) w = valW[k * 64 + ni];
        else if (seg <= 8) { int p = seg - 2; w = TW[p * 4096 + ni * 64 + k]; }
        else               w = Tb[ni * 64 + k];
        g_Wf16[idx] = __float2half_rn(w);
    } else if (idx < 40960 + 4096) {
        int i = idx - 40960; int n = i >> 6, k = i & 63;
        float w = d1W[k * 64 + n];
        __half h = __float2half_rn(w);
        g_D1h[i] = h; g_D1l[i] = __float2half_rn(w - __half2float(h));
    } else if (idx < 45056 + 2048) {
        int i = idx - 45056; int n = i >> 6, k = i & 63;
        float w = d2W[k * 32 + n];
        __half h = __float2half_rn(w);
        g_D2h[i] = h; g_D2l[i] = __float2half_rn(w - __half2float(h));
    } else if (idx < 47104 + 4096) {
        int i = idx - 47104; int n = i >> 6, k = i & 63;
        float w = (k < 32) ? d3W[k * 64 + n] : 0.f;
        __half h = __float2half_rn(w);
        g_D3h[i] = h; g_D3l[i] = __float2half_rn(w - __half2float(h));
    }
}

// ---- asm helpers ----
__device__ __forceinline__ u32 smem_u32(const void* p) {
    u32 a; asm("{ .reg .u64 t; cvta.to.shared.u64 t, %1; cvt.u32.u64 %0, t; }" : "=r"(a) : "l"(p));
    return a;
}
__device__ __forceinline__ void ldmx4(u32& r0, u32& r1, u32& r2, u32& r3, u32 addr) {
    asm volatile("ldmatrix.sync.aligned.m8n8.x4.shared.b16 {%0,%1,%2,%3}, [%4];"
                 : "=r"(r0), "=r"(r1), "=r"(r2), "=r"(r3) : "r"(addr));
}
__device__ __forceinline__ void mma16816(float* d, const u32* a, u32 b0, u32 b1) {
    asm volatile("mma.sync.aligned.m16n8k16.row.col.f32.f16.f16.f32 "
                 "{%0,%1,%2,%3}, {%4,%5,%6,%7}, {%8,%9}, {%0,%1,%2,%3};"
                 : "+f"(d[0]), "+f"(d[1]), "+f"(d[2]), "+f"(d[3])
                 : "r"(a[0]), "r"(a[1]), "r"(a[2]), "r"(a[3]), "r"(b0), "r"(b1));
}

// single-precision-operand segment GEMM (big GEMM): acc += A x W[n0..n0+63]
__device__ __forceinline__ void gemm_seg(float* acc, int n0, const u32 a[4][4],
                                         u32 sWb, int lane) {
    const int rowb = n0 + (lane & 7);
    const u32 roff = (u32)((lane >> 3) * 16);
#pragma unroll
    for (int f = 0; f < 8; f++) {
        u32 base = (u32)((rowb + f * 8) * 128) + roff;
        u32 b0, b1, b2, b3, b4, b5, b6, b7;
        ldmx4(b0, b1, b2, b3, sWb + SW128(base));
        ldmx4(b4, b5, b6, b7, sWb + SW128(base + 64));
        mma16816(acc + f * 4, a[0], b0, b1);
        mma16816(acc + f * 4, a[1], b2, b3);
        mma16816(acc + f * 4, a[2], b4, b5);
        mma16816(acc + f * 4, a[3], b6, b7);
    }
}

// split (hi/lo) MLP block: acc += Ah@Bh + Al@Bh + Ah@Bl
template<int NF, int NK>
__device__ __forceinline__ void mma_block(float (*acc)[4], const u32 (*ah)[4], const u32 (*al)[4],
                                          u32 sBh, u32 sBl, int lane) {
    const int rowb = lane & 7;
    const u32 roff = (u32)((lane >> 3) * 16);
#pragma unroll
    for (int f = 0; f < NF; f++) {
        u32 base = (u32)((rowb + f * 8) * 128) + roff;
        u32 bh[8], bl[8];
        ldmx4(bh[0], bh[1], bh[2], bh[3], sBh + SW128(base));
        ldmx4(bl[0], bl[1], bl[2], bl[3], sBl + SW128(base));
        if (NK == 4) {
            ldmx4(bh[4], bh[5], bh[6], bh[7], sBh + SW128(base + 64));
            ldmx4(bl[4], bl[5], bl[6], bl[7], sBl + SW128(base + 64));
        }
#pragma unroll
        for (int k = 0; k < NK; k++) {
            mma16816(acc[f], ah[k], bh[2*k], bh[2*k+1]);
            mma16816(acc[f], al[k], bh[2*k], bh[2*k+1]);
            mma16816(acc[f], ah[k], bl[2*k], bl[2*k+1]);
        }
    }
}

template<int NK>
__device__ __forceinline__ void load_afrags(u32 (*fr)[4], u32 buf, int rowa, u32 aoff) {
#pragma unroll
    for (int k = 0; k < NK; k++)
        ldmx4(fr[k][0], fr[k][1], fr[k][2], fr[k][3],
              buf + SW128((u32)(rowa * 128 + k * 32) + aoff));
}

__global__ void __launch_bounds__(THREADS, 1)
fused_kernel(const float* __restrict__ kv_in, const float* __restrict__ query,
             const float* __restrict__ key_b, const float* __restrict__ value_b,
             const float* __restrict__ d1b, const float* __restrict__ d2b,
             const float* __restrict__ d3b,
             const float* __restrict__ scale_p, float* __restrict__ out)
{
    extern __shared__ char smem[];
    const u32 smb  = smem_u32(smem);
    const u32 sWb  = smb + SM_W;
    const u32 sAb  = smb + SM_A;
    const u32 sXHb = smb + SM_XH;
    const u32 sXLb = smb + SM_XL;
    float* sKB = reinterpret_cast<float*>(smem + SM_KB);
    float* sVB = reinterpret_cast<float*>(smem + SM_VB);
    float* sB1 = reinterpret_cast<float*>(smem + SM_B1);
    float* sB2 = reinterpret_cast<float*>(smem + SM_B2);
    float* sB3 = reinterpret_cast<float*>(smem + SM_B3);

    const int tid  = threadIdx.x;
    const int lane = tid & 31;
    const int w    = tid >> 5;          // warp: tokens [16w, 16w+16)
    const int g    = lane >> 2;
    const int tg   = lane & 3;
    const int T0l  = 16 * w + g;        // local token rows this lane covers
    const int T1l  = T0l + 8;
    const int rowa = w * 16 + (lane & 15);
    const u32 aoff = (u32)(((lane >> 4) & 1) * 16);

    // ---- one-time staging (all swizzled copies use the same pattern) ----
    for (int i = tid; i < 5120; i += THREADS) {
        int row = i >> 3, ch = i & 7;
        *reinterpret_cast<uint4*>(smem + SM_W + SW128(row * 128 + ch * 16)) =
            reinterpret_cast<const uint4*>(g_Wf16)[i];
    }
    for (int i = tid; i < 512; i += THREADS) {
        int row = i >> 3, ch = i & 7;
        u32 off = SW128(row * 128 + ch * 16);
        *reinterpret_cast<uint4*>(smem + SM_D1H + off) = reinterpret_cast<const uint4*>(g_D1h)[i];
        *reinterpret_cast<uint4*>(smem + SM_D1L + off) = reinterpret_cast<const uint4*>(g_D1l)[i];
        *reinterpret_cast<uint4*>(smem + SM_D3H + off) = reinterpret_cast<const uint4*>(g_D3h)[i];
        *reinterpret_cast<uint4*>(smem + SM_D3L + off) = reinterpret_cast<const uint4*>(g_D3l)[i];
    }
    for (int i = tid; i < 256; i += THREADS) {
        int row = i >> 3, ch = i & 7;
        u32 off = SW128(row * 128 + ch * 16);
        *reinterpret_cast<uint4*>(smem + SM_D2H + off) = reinterpret_cast<const uint4*>(g_D2h)[i];
        *reinterpret_cast<uint4*>(smem + SM_D2L + off) = reinterpret_cast<const uint4*>(g_D2l)[i];
    }
    for (int i = tid; i < 64; i += THREADS) {
        sKB[i] = key_b[i]; sVB[i] = value_b[i];
        sB1[i] = d1b[i];   sB3[i] = d3b[i];
        if (i < 32) sB2[i] = d2b[i];
    }
    const float scale = __ldg(scale_p);

    const int tile0 = blockIdx.x;
    float4 pk[8];
    {
        const int base = tile0 * TM;
#pragma unroll
        for (int r = 0; r < 8; r++) {
            int idx = tid + r * THREADS;
            int t = idx >> 4, j4 = (idx & 15) << 2;
            pk[r] = *reinterpret_cast<const float4*>(kv_in + (size_t)(base + t) * 64 + j4);
        }
    }

    for (int tile = tile0; tile < NTILES; tile += GRID) {
        const int base = tile * TM;

        __syncthreads();   // prev tile A-frag reads complete (cross-warp commit below)
        // ---- commit kv -> f16 swizzled A ----
#pragma unroll
        for (int r = 0; r < 8; r++) {
            int idx = tid + r * THREADS;
            int t = idx >> 4, j4 = (idx & 15) << 2;
            __half2 h0 = __floats2half2_rn(pk[r].x, pk[r].y);
            __half2 h1 = __floats2half2_rn(pk[r].z, pk[r].w);
            uint2 o = make_uint2(*reinterpret_cast<u32*>(&h0), *reinterpret_cast<u32*>(&h1));
            *reinterpret_cast<uint2*>(smem + SM_A + SW128(t * 128 + j4 * 2)) = o;
        }
        // query coeffs for this lane's two tokens (c[7]=1 for Tb segment)
        float cA[8], cB[8];
        {
            const float* q0 = query + (size_t)(base + T0l) * 7;
            const float* q1 = q0 + 8 * 7;
#pragma unroll
            for (int p = 0; p < 7; p++) { cA[p] = __ldg(q0 + p); cB[p] = __ldg(q1 + p); }
            cA[7] = 1.f; cB[7] = 1.f;
        }
        __syncthreads();

        // ---- A fragments (once; reused for all 10 segments) ----
        u32 a[4][4];
        load_afrags<4>(a, sAb, rowa, aoff);

        // ---- big GEMM: k, v, folded hypernet q ----
        float accK[32], accV[32], accQ[32];
#pragma unroll
        for (int i = 0; i < 32; i++) { accK[i] = 0.f; accV[i] = 0.f; accQ[i] = 0.f; }
        gemm_seg(accK, 0,  a, sWb, lane);
        gemm_seg(accV, 64, a, sWb, lane);
        {
            const u32 roff = (u32)((lane >> 3) * 16);
#pragma unroll
            for (int si = 0; si < 8; si++) {
                const int rowb = 128 + si * 64 + (lane & 7);
                float ca = cA[si], cb = cB[si];
#pragma unroll
                for (int f = 0; f < 8; f++) {
                    float t[4] = {0.f, 0.f, 0.f, 0.f};
                    u32 bbase = (u32)((rowb + f * 8) * 128) + roff;
                    u32 b0, b1, b2, b3, b4, b5, b6, b7;
                    ldmx4(b0, b1, b2, b3, sWb + SW128(bbase));
                    ldmx4(b4, b5, b6, b7, sWb + SW128(bbase + 64));
                    mma16816(t, a[0], b0, b1);
                    mma16816(t, a[1], b2, b3);
                    mma16816(t, a[2], b4, b5);
                    mma16816(t, a[3], b6, b7);
                    accQ[f*4+0] += ca * t[0];
                    accQ[f*4+1] += ca * t[1];
                    accQ[f*4+2] += cb * t[2];
                    accQ[f*4+3] += cb * t[3];
                }
            }
        }

        // ---- epilogue: normalize(q*k) * softmax(v*scale) ----
        float ss0 = 0.f, es0 = 0.f, ss1 = 0.f, es1 = 0.f;
#pragma unroll
        for (int f = 0; f < 8; f++) {
            int col = f * 8 + 2 * tg;
            float2 kb2 = *reinterpret_cast<const float2*>(sKB + col);
            float2 vb2 = *reinterpret_cast<const float2*>(sVB + col);
            float a0 = accQ[f*4+0] * (accK[f*4+0] + kb2.x);
            float a1 = accQ[f*4+1] * (accK[f*4+1] + kb2.y);
            float a2 = accQ[f*4+2] * (accK[f*4+2] + kb2.x);
            float a3 = accQ[f*4+3] * (accK[f*4+3] + kb2.y);
            ss0 += a0 * a0 + a1 * a1;
            ss1 += a2 * a2 + a3 * a3;
            float s0 = __expf((accV[f*4+0] + vb2.x) * scale);
            float s1 = __expf((accV[f*4+1] + vb2.y) * scale);
            float s2 = __expf((accV[f*4+2] + vb2.x) * scale);
            float s3 = __expf((accV[f*4+3] + vb2.y) * scale);
            es0 += s0 + s1; es1 += s2 + s3;
            accQ[f*4+0] = a0; accQ[f*4+1] = a1; accQ[f*4+2] = a2; accQ[f*4+3] = a3;
            accV[f*4+0] = s0; accV[f*4+1] = s1; accV[f*4+2] = s2; accV[f*4+3] = s3;
        }
        ss0 += __shfl_xor_sync(0xffffffffu, ss0, 1);
        ss0 += __shfl_xor_sync(0xffffffffu, ss0, 2);
        ss1 += __shfl_xor_sync(0xffffffffu, ss1, 1);
        ss1 += __shfl_xor_sync(0xffffffffu, ss1, 2);
        es0 += __shfl_xor_sync(0xffffffffu, es0, 1);
        es0 += __shfl_xor_sync(0xffffffffu, es0, 2);
        es1 += __shfl_xor_sync(0xffffffffu, es1, 1);
        es1 += __shfl_xor_sync(0xffffffffu, es1, 2);
        float sc0 = (1.0f / fmaxf(sqrtf(ss0), 1e-8f)) / es0;
        float sc1 = (1.0f / fmaxf(sqrtf(ss1), 1e-8f)) / es1;

        // x -> hi/lo f16 activation buffers (own token rows only; no sync needed)
#pragma unroll
        for (int f = 0; f < 8; f++) {
            int col = f * 8 + 2 * tg;
            float v00 = accQ[f*4+0] * accV[f*4+0] * sc0;
            float v01 = accQ[f*4+1] * accV[f*4+1] * sc0;
            float v10 = accQ[f*4+2] * accV[f*4+2] * sc1;
            float v11 = accQ[f*4+3] * accV[f*4+3] * sc1;
            {
                __half h0 = __float2half_rn(v00), h1 = __float2half_rn(v01);
                __half2 hh = __halves2half2(h0, h1);
                __half2 ll = __halves2half2(__float2half_rn(v00 - __half2float(h0)),
                                            __float2half_rn(v01 - __half2float(h1)));
                u32 off = SW128((u32)(T0l * 128 + col * 2));
                *reinterpret_cast<u32*>(smem + SM_XH + off) = *reinterpret_cast<u32*>(&hh);
                *reinterpret_cast<u32*>(smem + SM_XL + off) = *reinterpret_cast<u32*>(&ll);
            }
            {
                __half h0 = __float2half_rn(v10), h1 = __float2half_rn(v11);
                __half2 hh = __halves2half2(h0, h1);
                __half2 ll = __halves2half2(__float2half_rn(v10 - __half2float(h0)),
                                            __float2half_rn(v11 - __half2float(h1)));
                u32 off = SW128((u32)(T1l * 128 + col * 2));
                *reinterpret_cast<u32*>(smem + SM_XH + off) = *reinterpret_cast<u32*>(&hh);
                *reinterpret_cast<u32*>(smem + SM_XL + off) = *reinterpret_cast<u32*>(&ll);
            }
        }

        // ---- prefetch next tile kv ----
        {
            int nt = tile + GRID;
            int pbase = (nt < NTILES ? nt : tile0) * TM;
#pragma unroll
            for (int r = 0; r < 8; r++) {
                int idx = tid + r * THREADS;
                int t = idx >> 4, j4 = (idx & 15) << 2;
                pk[r] = *reinterpret_cast<const float4*>(kv_in + (size_t)(pbase + t) * 64 + j4);
            }
        }

        // ================= MLP chain (sync-free: own rows only) =================
        u32 ah[4][4], al[4][4];

        // ---- MLP1: h1 = relu(x @ d1 + b1), split mma ----
        load_afrags<4>(ah, sXHb, rowa, aoff);
        load_afrags<4>(al, sXLb, rowa, aoff);
        {
            float acc[8][4];
#pragma unroll
            for (int f = 0; f < 8; f++) { acc[f][0]=0; acc[f][1]=0; acc[f][2]=0; acc[f][3]=0; }
            mma_block<8, 4>(acc, ah, al, smb + SM_D1H, smb + SM_D1L, lane);
#pragma unroll
            for (int f = 0; f < 8; f++) {
                int col = f * 8 + 2 * tg;
                float2 b = *reinterpret_cast<const float2*>(sB1 + col);
                float v00 = fmaxf(acc[f][0] + b.x, 0.f), v01 = fmaxf(acc[f][1] + b.y, 0.f);
                float v10 = fmaxf(acc[f][2] + b.x, 0.f), v11 = fmaxf(acc[f][3] + b.y, 0.f);
                {
                    __half h0 = __float2half_rn(v00), h1 = __float2half_rn(v01);
                    __half2 hh = __halves2half2(h0, h1);
                    __half2 ll = __halves2half2(__float2half_rn(v00 - __half2float(h0)),
                                                __float2half_rn(v01 - __half2float(h1)));
                    u32 off = SW128((u32)(T0l * 128 + col * 2));
                    *reinterpret_cast<u32*>(smem + SM_XH + off) = *reinterpret_cast<u32*>(&hh);
                    *reinterpret_cast<u32*>(smem + SM_XL + off) = *reinterpret_cast<u32*>(&ll);
                }
                {
                    __half h0 = __float2half_rn(v10), h1 = __float2half_rn(v11);
                    __half2 hh = __halves2half2(h0, h1);
                    __half2 ll = __halves2half2(__float2half_rn(v10 - __half2float(h0)),
                                                __float2half_rn(v11 - __half2float(h1)));
                    u32 off = SW128((u32)(T1l * 128 + col * 2));
                    *reinterpret_cast<u32*>(smem + SM_XH + off) = *reinterpret_cast<u32*>(&hh);
                    *reinterpret_cast<u32*>(smem + SM_XL + off) = *reinterpret_cast<u32*>(&ll);
                }
            }
        }

        // ---- MLP2: h2 = relu(h1 @ d2 + b2), 32 cols ----
        load_afrags<4>(ah, sXHb, rowa, aoff);
        load_afrags<4>(al, sXLb, rowa, aoff);
        {
            float acc[4][4];
#pragma unroll
            for (int f = 0; f < 4; f++) { acc[f][0]=0; acc[f][1]=0; acc[f][2]=0; acc[f][3]=0; }
            mma_block<4, 4>(acc, ah, al, smb + SM_D2H, smb + SM_D2L, lane);
#pragma unroll
            for (int f = 0; f < 4; f++) {
                int col = f * 8 + 2 * tg;
                float2 b = *reinterpret_cast<const float2*>(sB2 + col);
                float v00 = fmaxf(acc[f][0] + b.x, 0.f), v01 = fmaxf(acc[f][1] + b.y, 0.f);
                float v10 = fmaxf(acc[f][2] + b.x, 0.f), v11 = fmaxf(acc[f][3] + b.y, 0.f);
                {
                    __half h0 = __float2half_rn(v00), h1 = __float2half_rn(v01);
                    __half2 hh = __halves2half2(h0, h1);
                    __half2 ll = __halves2half2(__float2half_rn(v00 - __half2float(h0)),
                                                __float2half_rn(v01 - __half2float(h1)));
                    u32 off = SW128((u32)(T0l * 128 + col * 2));
                    *reinterpret_cast<u32*>(smem + SM_XH + off) = *reinterpret_cast<u32*>(&hh);
                    *reinterpret_cast<u32*>(smem + SM_XL + off) = *reinterpret_cast<u32*>(&ll);
                }
                {
                    __half h0 = __float2half_rn(v10), h1 = __float2half_rn(v11);
                    __half2 hh = __halves2half2(h0, h1);
                    __half2 ll = __halves2half2(__float2half_rn(v10 - __half2float(h0)),
                                                __float2half_rn(v11 - __half2float(h1)));
                    u32 off = SW128((u32)(T1l * 128 + col * 2));
                    *reinterpret_cast<u32*>(smem + SM_XH + off) = *reinterpret_cast<u32*>(&hh);
                    *reinterpret_cast<u32*>(smem + SM_XL + off) = *reinterpret_cast<u32*>(&ll);
                }
            }
        }

        // ---- MLP3: out = h2 @ d3 + b3 (K=32), store to gmem from fragments ----
        load_afrags<2>(ah, sXHb, rowa, aoff);
        load_afrags<2>(al, sXLb, rowa, aoff);
        {
            float acc[8][4];
#pragma unroll
            for (int f = 0; f < 8; f++) { acc[f][0]=0; acc[f][1]=0; acc[f][2]=0; acc[f][3]=0; }
            mma_block<8, 2>(acc, ah, al, smb + SM_D3H, smb + SM_D3L, lane);
#pragma unroll
            for (int f = 0; f < 8; f++) {
                int col = f * 8 + 2 * tg;
                float2 b = *reinterpret_cast<const float2*>(sB3 + col);
                *reinterpret_cast<float2*>(out + (size_t)(base + T0l) * 64 + col) =
                    make_float2(acc[f][0] + b.x, acc[f][1] + b.y);
                *reinterpret_cast<float2*>(out + (size_t)(base + T1l) * 64 + col) =
                    make_float2(acc[f][2] + b.x, acc[f][3] + b.y);
            }
        }
    }
}

extern "C" void kernel_launch(void* const* d_in, const int* in_sizes, int n_in,
                              void* d_out, int out_size) {
    const float* kv      = (const float*)d_in[0];
    const float* query   = (const float*)d_in[1];
    const float* keyW    = (const float*)d_in[2];
    const float* keyb    = (const float*)d_in[3];
    const float* valW    = (const float*)d_in[4];
    const float* valb    = (const float*)d_in[5];
    const float* TW      = (const float*)d_in[6];
    const float* Tb      = (const float*)d_in[7];
    const float* d1W     = (const float*)d_in[8];
    const float* d1b     = (const float*)d_in[9];
    const float* d2W     = (const float*)d_in[10];
    const float* d2b     = (const float*)d_in[11];
    const float* d3W     = (const float*)d_in[12];
    const float* d3b     = (const float*)d_in[13];
    const float* scale   = (const float*)d_in[14];
    float* out           = (float*)d_out;

    cudaFuncSetAttribute(fused_kernel, cudaFuncAttributeMaxDynamicSharedMemorySize, SM_TOTAL);

    prep_kernel<<<200, 256>>>(keyW, valW, TW, Tb, d1W, d2W, d3W);
    fused_kernel<<<GRID, THREADS, SM_TOTAL>>>(kv, query, keyb, valb,
                                              d1b, d2b, d3b, scale, out);
}